// round 9
// baseline (speedup 1.0000x reference)
#include <cuda_runtime.h>
#include <cuda.h>
#include <math.h>
#include <cstdint>

// ---------------- problem constants ----------------
#define NTOK   4096          // B*S
#define HDIM   4096
#define NEXP   8
#define TOPK   2
#define CAP    1536
#define NSEL   (NTOK*TOPK)

#define DISPATCH_ELEMS  ((long long)NTOK*NEXP*CAP)
#define PROBS_OFF       (2LL*DISPATCH_ELEMS)
#define AUX_OFF         (PROBS_OFF + (long long)NTOK*NEXP)

#define KW (HDIM / 2)        // words (fp16x2) per row

// ---------------- device scratch ----------------
__device__ uint32_t g_AhiW[(size_t)NTOK * KW];   // x hi, fp16x2 words [M][K/2]
__device__ uint32_t g_AloW[(size_t)NTOK * KW];   // x lo*2048
__device__ uint32_t g_BhiW[(size_t)HDIM * KW];   // W1^T hi  [N][K/2]
__device__ uint32_t g_BloW[(size_t)HDIM * KW];   // W1^T lo*2048
__device__ float g_h[(size_t)NTOK * HDIM];
__device__ float g_logits[NTOK * NEXP];
__device__ int   g_flat_idx[NSEL];
__device__ float g_flat_prob[NSEL];
__device__ int   g_pos[NSEL];
__device__ int   g_counts[NEXP];

// ---------------- helpers ----------------
__device__ __forceinline__ void cpasync16(uint32_t dst, const void* src) {
    asm volatile("cp.async.cg.shared.global [%0], [%1], 16;\n" :: "r"(dst), "l"(src));
}
#define CP_COMMIT() asm volatile("cp.async.commit_group;\n" ::: "memory")
#define CP_WAIT(n)  asm volatile("cp.async.wait_group %0;\n" :: "n"(n) : "memory")

__device__ __forceinline__ uint32_t smem_u32(const void* p) {
    uint32_t a;
    asm("{ .reg .u64 t; cvta.to.shared.u64 t, %1; cvt.u32.u64 %0, t; }" : "=r"(a) : "l"(p));
    return a;
}

// keep top 10 explicit mantissa bits (exactly fp16-representable in normal range)
__device__ __forceinline__ float hi10(float v) {
    return __uint_as_float(__float_as_uint(v) & 0xFFFFE000u);
}
// pack {low half = eve, high half = odd} as f16x2
__device__ __forceinline__ uint32_t pk(float eve, float odd) {
    uint32_t d;
    asm("cvt.rn.f16x2.f32 %0, %1, %2;" : "=r"(d) : "f"(odd), "f"(eve));
    return d;
}

// mma.sync m16n8k16 fp16 inputs, fp32 accum. Base ISA (sm_80+).
__device__ __forceinline__ void mma_f16(float c[4],
                                        uint32_t a0, uint32_t a1, uint32_t a2, uint32_t a3,
                                        uint32_t b0, uint32_t b1) {
    asm volatile(
        "mma.sync.aligned.m16n8k16.row.col.f32.f16.f16.f32 "
        "{%0,%1,%2,%3}, {%4,%5,%6,%7}, {%8,%9}, {%0,%1,%2,%3};"
        : "+f"(c[0]), "+f"(c[1]), "+f"(c[2]), "+f"(c[3])
        : "r"(a0), "r"(a1), "r"(a2), "r"(a3), "r"(b0), "r"(b1));
}

#define SCALE_UP   2048.0f
#define SCALE_DOWN 4.8828125e-4f      // 1/2048

// ---------------- prep A: x -> Ahi/Alo fp16 words ----------------
__global__ void prep_A(const float4* __restrict__ x, uint2* __restrict__ hiw,
                       uint2* __restrict__ low, int n4) {
    int i = blockIdx.x * blockDim.x + threadIdx.x;
    int stride = gridDim.x * blockDim.x;
    for (; i < n4; i += stride) {
        float4 v = x[i];
        float h0 = hi10(v.x), h1 = hi10(v.y), h2 = hi10(v.z), h3 = hi10(v.w);
        uint2 hw, lw;
        hw.x = pk(h0, h1);
        hw.y = pk(h2, h3);
        lw.x = pk((v.x - h0) * SCALE_UP, (v.y - h1) * SCALE_UP);
        lw.y = pk((v.z - h2) * SCALE_UP, (v.w - h3) * SCALE_UP);
        hiw[i] = hw;
        low[i] = lw;
    }
}

// ---------------- prep B: W1 [K,N] -> Bt hi/lo fp16 words [N][K/2] ----------------
__global__ void prep_B(const float* __restrict__ W1, uint32_t* __restrict__ hiw,
                       uint32_t* __restrict__ low) {
    __shared__ float tile[32][33];
    const int n0 = blockIdx.x * 32, k0 = blockIdx.y * 32;
    const int tx = threadIdx.x, ty = threadIdx.y;    // (32,8)
    #pragma unroll
    for (int i = 0; i < 4; i++)
        tile[ty + i * 8][tx] = W1[(size_t)(k0 + ty + i * 8) * HDIM + n0 + tx];
    __syncthreads();
    const int half = tx >> 4;       // 0 = hi, 1 = lo
    const int j = tx & 15;          // word index in 32-k block
    #pragma unroll
    for (int i = 0; i < 4; i++) {
        const int nl = ty + i * 8;
        float v0 = tile[2 * j][nl], v1 = tile[2 * j + 1][nl];
        float h0 = hi10(v0), h1 = hi10(v1);
        size_t off = (size_t)(n0 + nl) * KW + (k0 >> 1) + j;
        if (half == 0) hiw[off] = pk(h0, h1);
        else           low[off] = pk((v0 - h0) * SCALE_UP, (v1 - h1) * SCALE_UP);
    }
}

// ---------------- GEMM1: h = relu(x @ W1 + b1), precomputed fp16 split ----------------
// acc_hh += hiA*hiB ; acc_cr += hiA*loB + loA*hiB ; h = acc_hh + acc_cr/2048 + bias.
#define BM 128
#define BN 128
#define BK 32                 // fp16 elems per chunk = 16 words
#define SW 20                 // words per smem row (16 data + 4 pad) -> conflict-free
#define TILEB (128 * SW * 4)  // 10240 bytes per tile
#define STAGEBYTES (4 * TILEB)        // 40960
#define GSMEM (2 * STAGEBYTES)        // 81920
#define ZPT 96                        // fused zero chunks per CTA

__global__ __launch_bounds__(256) void gemm1_tc(
    const float* __restrict__ bias, float* __restrict__ C,
    float4* __restrict__ zout)
{
    extern __shared__ char smem[];
    const int tid = threadIdx.x;
    const int warp = tid >> 5, lane = tid & 31;
    const int wm = (warp & 1) * 64;       // warp m-offset
    const int wn = (warp >> 1) * 32;      // warp n-offset
    const int row0 = blockIdx.y * BM;
    const int col0 = blockIdx.x * BN;
    const int r = lane >> 2, cq = lane & 3;
    const int ctalin = blockIdx.y * 32 + blockIdx.x;   // 0..1023

    const uint32_t sb = smem_u32(smem);

    if (ctalin == 0 && tid < NEXP) g_counts[tid] = 0;

    float acc_hh[4][4][4];
    float acc_cr[4][4][4];
    #pragma unroll
    for (int i = 0; i < 4; i++)
        #pragma unroll
        for (int j = 0; j < 4; j++)
            #pragma unroll
            for (int f = 0; f < 4; f++) { acc_hh[i][j][f] = 0.f; acc_cr[i][j][f] = 0.f; }

    // fill one stage: 4 tiles (Ahi, Alo, Bhi, Blo), each 128 rows x 16 words
    auto fill = [&](int buf, int c) {
        const uint32_t st = sb + buf * STAGEBYTES;
        const int kw = c * 16;            // word offset in K
        #pragma unroll
        for (int t = 0; t < 8; t++) {
            int o = tid + t * 256;        // 0..2047
            int tile_id = o >> 9;         // 0..3
            int within = o & 511;
            int rr = within >> 2, c16 = within & 3;
            const uint32_t* src;
            if (tile_id == 0)      src = g_AhiW + (size_t)(row0 + rr) * KW + kw + c16 * 4;
            else if (tile_id == 1) src = g_AloW + (size_t)(row0 + rr) * KW + kw + c16 * 4;
            else if (tile_id == 2) src = g_BhiW + (size_t)(col0 + rr) * KW + kw + c16 * 4;
            else                   src = g_BloW + (size_t)(col0 + rr) * KW + kw + c16 * 4;
            cpasync16(st + tile_id * TILEB + (rr * SW + c16 * 4) * 4, src);
        }
    };

    fill(0, 0);
    CP_COMMIT();

    const float4 z4 = make_float4(0.f, 0.f, 0.f, 0.f);
    const long long zbase = (long long)ctalin * (ZPT * 256) + tid;

    const int NCHUNK = HDIM / BK;   // 128
    for (int c = 0; c < NCHUNK; ++c) {
        if (c < ZPT) zout[zbase + (long long)c * 256] = z4;

        if (c + 1 < NCHUNK) { fill((c + 1) & 1, c + 1); CP_COMMIT(); CP_WAIT(1); }
        else                { CP_WAIT(0); }
        __syncthreads();

        const uint32_t* AhiS = (const uint32_t*)(smem + (c & 1) * STAGEBYTES);
        const uint32_t* AloS = AhiS + TILEB / 4;
        const uint32_t* BhiS = AloS + TILEB / 4;
        const uint32_t* BloS = BhiS + TILEB / 4;

        #pragma unroll
        for (int kk = 0; kk < 2; kk++) {       // two k16 steps
            const int kwb = kk * 8;            // word base within chunk

            // A frags: a0=(row,cq) a1=(row+8,cq) a2=(row,cq+4) a3=(row+8,cq+4) [words]
            uint32_t ahi[4][4], alo[4][4];
            #pragma unroll
            for (int mt = 0; mt < 4; mt++) {
                const int base = (wm + mt * 16 + r) * SW + kwb + cq;
                ahi[mt][0] = AhiS[base];
                ahi[mt][1] = AhiS[base + 8 * SW];
                ahi[mt][2] = AhiS[base + 4];
                ahi[mt][3] = AhiS[base + 8 * SW + 4];
                alo[mt][0] = AloS[base];
                alo[mt][1] = AloS[base + 8 * SW];
                alo[mt][2] = AloS[base + 4];
                alo[mt][3] = AloS[base + 8 * SW + 4];
            }
            // B frags: b0=(n,cq) b1=(n,cq+4) [words], n = wn+nt*8+r
            uint32_t bhi[4][2], blo[4][2];
            #pragma unroll
            for (int nt = 0; nt < 4; nt++) {
                const int base = (wn + nt * 8 + r) * SW + kwb + cq;
                bhi[nt][0] = BhiS[base];
                bhi[nt][1] = BhiS[base + 4];
                blo[nt][0] = BloS[base];
                blo[nt][1] = BloS[base + 4];
            }
            // 3 passes: hh, hi*lo, lo*hi
            #pragma unroll
            for (int mt = 0; mt < 4; mt++)
                #pragma unroll
                for (int nt = 0; nt < 4; nt++)
                    mma_f16(acc_hh[mt][nt], ahi[mt][0], ahi[mt][1], ahi[mt][2], ahi[mt][3],
                            bhi[nt][0], bhi[nt][1]);
            #pragma unroll
            for (int mt = 0; mt < 4; mt++)
                #pragma unroll
                for (int nt = 0; nt < 4; nt++)
                    mma_f16(acc_cr[mt][nt], ahi[mt][0], ahi[mt][1], ahi[mt][2], ahi[mt][3],
                            blo[nt][0], blo[nt][1]);
            #pragma unroll
            for (int mt = 0; mt < 4; mt++)
                #pragma unroll
                for (int nt = 0; nt < 4; nt++)
                    mma_f16(acc_cr[mt][nt], alo[mt][0], alo[mt][1], alo[mt][2], alo[mt][3],
                            bhi[nt][0], bhi[nt][1]);
        }
        __syncthreads();
    }

    // ---- epilogue: relu(hh + cr/2048 + bias) -> C ----
    #pragma unroll
    for (int mt = 0; mt < 4; mt++) {
        #pragma unroll
        for (int nt = 0; nt < 4; nt++) {
            int col = col0 + wn + nt * 8 + 2 * cq;
            float bx = __ldg(bias + col), by = __ldg(bias + col + 1);
            int rowa = row0 + wm + mt * 16 + r;
            float2 v0, v1;
            v0.x = fmaxf(acc_hh[mt][nt][0] + acc_cr[mt][nt][0] * SCALE_DOWN + bx, 0.f);
            v0.y = fmaxf(acc_hh[mt][nt][1] + acc_cr[mt][nt][1] * SCALE_DOWN + by, 0.f);
            v1.x = fmaxf(acc_hh[mt][nt][2] + acc_cr[mt][nt][2] * SCALE_DOWN + bx, 0.f);
            v1.y = fmaxf(acc_hh[mt][nt][3] + acc_cr[mt][nt][3] * SCALE_DOWN + by, 0.f);
            *(float2*)(C + (size_t)rowa * HDIM + col) = v0;
            *(float2*)(C + (size_t)(rowa + 8) * HDIM + col) = v1;
        }
    }
}

// ---------------- GEMM2: logits = h @ W2 + b2 (one warp per token) ----------------
__global__ void gemm2_kernel(const float* __restrict__ h, const float* __restrict__ W2,
                             const float* __restrict__ b2, float* __restrict__ logits)
{
    int warp = (blockIdx.x * blockDim.x + threadIdx.x) >> 5;
    int lane = threadIdx.x & 31;
    if (warp >= NTOK) return;
    const float* hr = h + (size_t)warp * HDIM;

    float acc[NEXP];
    #pragma unroll
    for (int e = 0; e < NEXP; e++) acc[e] = 0.f;

    for (int k0 = lane * 4; k0 < HDIM; k0 += 128) {
        float4 hv = *(const float4*)(hr + k0);
        float hvv[4] = {hv.x, hv.y, hv.z, hv.w};
        #pragma unroll
        for (int j = 0; j < 4; j++) {
            const float* w = W2 + (size_t)(k0 + j) * NEXP;
            float4 w0 = *(const float4*)w;
            float4 w1 = *(const float4*)(w + 4);
            acc[0] += hvv[j] * w0.x; acc[1] += hvv[j] * w0.y;
            acc[2] += hvv[j] * w0.z; acc[3] += hvv[j] * w0.w;
            acc[4] += hvv[j] * w1.x; acc[5] += hvv[j] * w1.y;
            acc[6] += hvv[j] * w1.z; acc[7] += hvv[j] * w1.w;
        }
    }
    #pragma unroll
    for (int e = 0; e < NEXP; e++) {
        #pragma unroll
        for (int off = 16; off > 0; off >>= 1)
            acc[e] += __shfl_down_sync(0xffffffffu, acc[e], off);
    }
    if (lane == 0) {
        #pragma unroll
        for (int e = 0; e < NEXP; e++)
            logits[warp * NEXP + e] = acc[e] + b2[e];
    }
}

// ---------------- softmax + top-2 ----------------
__global__ void topk_kernel(const float* __restrict__ logits, float* __restrict__ probs_out)
{
    int t = blockIdx.x * blockDim.x + threadIdx.x;
    if (t >= NTOK) return;
    float l[NEXP];
    float m = -1e30f;
    #pragma unroll
    for (int e = 0; e < NEXP; e++) { l[e] = logits[t * NEXP + e]; m = fmaxf(m, l[e]); }
    float s = 0.f;
    #pragma unroll
    for (int e = 0; e < NEXP; e++) { l[e] = expf(l[e] - m); s += l[e]; }
    float inv = 1.f / s;
    float p[NEXP];
    #pragma unroll
    for (int e = 0; e < NEXP; e++) { p[e] = l[e] * inv; probs_out[t * NEXP + e] = p[e]; }

    int i1 = 0; float p1 = p[0];
    #pragma unroll
    for (int e = 1; e < NEXP; e++) if (p[e] > p1) { p1 = p[e]; i1 = e; }
    int i2 = -1; float p2 = -1.f;
    #pragma unroll
    for (int e = 0; e < NEXP; e++) if (e != i1 && p[e] > p2) { p2 = p[e]; i2 = e; }

    float norm = 1.f / (p1 + p2 + 1e-8f);
    g_flat_idx[2 * t + 0] = i1;
    g_flat_idx[2 * t + 1] = i2;
    g_flat_prob[2 * t + 0] = p1 * norm;
    g_flat_prob[2 * t + 1] = p2 * norm;
    atomicAdd(&g_counts[i1], 1);
    atomicAdd(&g_counts[i2], 1);
}

// ---------------- exclusive per-expert position scan ----------------
__device__ __forceinline__ uint4 add4(uint4 a, uint4 b) {
    return make_uint4(a.x + b.x, a.y + b.y, a.z + b.z, a.w + b.w);
}
__device__ __forceinline__ uint4 sub4(uint4 a, uint4 b) {
    return make_uint4(a.x - b.x, a.y - b.y, a.z - b.z, a.w - b.w);
}
__global__ __launch_bounds__(1024) void scan_kernel()
{
    const int tid = threadIdx.x;
    const int lane = tid & 31, wid = tid >> 5;

    int e[8];
    uint4 pre[8];
    uint4 run = make_uint4(0, 0, 0, 0);
    #pragma unroll
    for (int i = 0; i < 8; i++) {
        e[i] = g_flat_idx[tid * 8 + i];
        pre[i] = run;
        unsigned word = (unsigned)e[i] >> 1;
        unsigned add = 1u << ((e[i] & 1) * 16);
        if (word == 0) run.x += add;
        else if (word == 1) run.y += add;
        else if (word == 2) run.z += add;
        else run.w += add;
    }
    const uint4 own = run;

    uint4 incl = own;
    #pragma unroll
    for (int off = 1; off < 32; off <<= 1) {
        unsigned vx = __shfl_up_sync(0xffffffffu, incl.x, off);
        unsigned vy = __shfl_up_sync(0xffffffffu, incl.y, off);
        unsigned vz = __shfl_up_sync(0xffffffffu, incl.z, off);
        unsigned vw = __shfl_up_sync(0xffffffffu, incl.w, off);
        if (lane >= off) { incl.x += vx; incl.y += vy; incl.z += vz; incl.w += vw; }
    }

    __shared__ uint4 wtot[32];
    if (lane == 31) wtot[wid] = incl;
    __syncthreads();
    if (wid == 0) {
        uint4 v = wtot[lane];
        uint4 inc2 = v;
        #pragma unroll
        for (int off = 1; off < 32; off <<= 1) {
            unsigned vx = __shfl_up_sync(0xffffffffu, inc2.x, off);
            unsigned vy = __shfl_up_sync(0xffffffffu, inc2.y, off);
            unsigned vz = __shfl_up_sync(0xffffffffu, inc2.z, off);
            unsigned vw = __shfl_up_sync(0xffffffffu, inc2.w, off);
            if (lane >= off) { inc2.x += vx; inc2.y += vy; inc2.z += vz; inc2.w += vw; }
        }
        wtot[lane] = sub4(inc2, v);
    }
    __syncthreads();

    const uint4 base = add4(wtot[wid], sub4(incl, own));
    #pragma unroll
    for (int i = 0; i < 8; i++) {
        uint4 tot = add4(base, pre[i]);
        unsigned word = (unsigned)e[i] >> 1;
        unsigned w = (word == 0) ? tot.x : (word == 1) ? tot.y : (word == 2) ? tot.z : tot.w;
        g_pos[tid * 8 + i] = (int)((w >> ((e[i] & 1) * 16)) & 0xFFFFu);
    }
}

// ---------------- scatter ----------------
__global__ void scatter_kernel(float* __restrict__ dispatch, float* __restrict__ combine)
{
    int n = blockIdx.x * blockDim.x + threadIdx.x;
    if (n >= NSEL) return;
    int p = g_pos[n];
    if (p < CAP) {
        int tok = n >> 1;
        int e = g_flat_idx[n];
        size_t off = ((size_t)tok * NEXP + e) * CAP + p;
        dispatch[off] = 1.0f;
        combine[off] = g_flat_prob[n];
    }
}

// ---------------- aux loss ----------------
__global__ void aux_kernel(const float* __restrict__ probs, float* __restrict__ aux_out)
{
    __shared__ float sh[256];
    const int tid = threadIdx.x;
    float local[NEXP];
    #pragma unroll
    for (int e = 0; e < NEXP; e++) local[e] = 0.f;
    for (int t = tid; t < NTOK; t += 256) {
        #pragma unroll
        for (int e = 0; e < NEXP; e++) local[e] += probs[t * NEXP + e];
    }
    float aux = 0.f;
    for (int e = 0; e < NEXP; e++) {
        sh[tid] = local[e];
        __syncthreads();
        for (int s = 128; s > 0; s >>= 1) {
            if (tid < s) sh[tid] += sh[tid + s];
            __syncthreads();
        }
        if (tid == 0)
            aux += (sh[0] / (float)NTOK) * ((float)g_counts[e] / (float)NSEL) * (float)NEXP;
        __syncthreads();
    }
    if (tid == 0) *aux_out = aux;
}

// ---------------- launch ----------------
extern "C" void kernel_launch(void* const* d_in, const int* in_sizes, int n_in,
                              void* d_out, int out_size)
{
    const float* x  = (const float*)d_in[0];
    const float* W1 = (const float*)d_in[1];
    const float* b1 = (const float*)d_in[2];
    const float* W2 = (const float*)d_in[3];
    const float* b2 = (const float*)d_in[4];

    float* out      = (float*)d_out;
    float* dispatch = out;
    float* combine  = out + DISPATCH_ELEMS;
    float* probs    = out + PROBS_OFF;
    float* aux      = out + AUX_OFF;

    uint32_t* d_AhiW; cudaGetSymbolAddress((void**)&d_AhiW, g_AhiW);
    uint32_t* d_AloW; cudaGetSymbolAddress((void**)&d_AloW, g_AloW);
    uint32_t* d_BhiW; cudaGetSymbolAddress((void**)&d_BhiW, g_BhiW);
    uint32_t* d_BloW; cudaGetSymbolAddress((void**)&d_BloW, g_BloW);
    float* d_h;      cudaGetSymbolAddress((void**)&d_h, g_h);
    float* d_logits; cudaGetSymbolAddress((void**)&d_logits, g_logits);

    static bool attr_set = false;
    if (!attr_set) {
        cudaFuncSetAttribute(gemm1_tc, cudaFuncAttributeMaxDynamicSharedMemorySize, GSMEM);
        attr_set = true;
    }

    // 1) prep: fp16 hi/lo split of x and W1^T (once, instead of per-tile)
    prep_A<<<2048, 256>>>((const float4*)x, (uint2*)d_AhiW, (uint2*)d_AloW,
                          NTOK * HDIM / 4);
    prep_B<<<dim3(HDIM / 32, HDIM / 32), dim3(32, 8)>>>(W1, d_BhiW, d_BloW);

    // 2) GEMM1 (fp16 split mma.sync m16n8k16) + fused output zeroing
    gemm1_tc<<<dim3(HDIM / BN, NTOK / BM), 256, GSMEM>>>(b1, d_h, (float4*)out);

    // 3) GEMM2
    gemm2_kernel<<<NTOK / 8, 256>>>(d_h, W2, b2, d_logits);

    // 4) softmax + top-2
    topk_kernel<<<NTOK / 256, 256>>>(d_logits, probs);

    // 5) capacity position scan
    scan_kernel<<<1, 1024>>>();

    // 6) scatter
    scatter_kernel<<<NSEL / 256, 256>>>(dispatch, combine);

    // 7) aux loss
    aux_kernel<<<1, 256>>>(probs, aux);
}

// round 10
// speedup vs baseline: 1.5526x; 1.5526x over previous
#include <cuda_runtime.h>
#include <cuda.h>
#include <math.h>
#include <cstdint>

// ---------------- problem constants ----------------
#define NTOK   4096          // B*S
#define HDIM   4096
#define NEXP   8
#define TOPK   2
#define CAP    1536
#define NSEL   (NTOK*TOPK)

#define DISPATCH_ELEMS  ((long long)NTOK*NEXP*CAP)
#define PROBS_OFF       (2LL*DISPATCH_ELEMS)
#define AUX_OFF         (PROBS_OFF + (long long)NTOK*NEXP)

// ---------------- device scratch ----------------
__device__ float g_h[(size_t)NTOK * HDIM];
__device__ float g_logits[NTOK * NEXP];
__device__ int   g_flat_idx[NSEL];
__device__ float g_flat_prob[NSEL];
__device__ int   g_pos[NSEL];
__device__ int   g_counts[NEXP];

// ---------------- helpers ----------------
__device__ __forceinline__ void cpasync16(uint32_t dst, const void* src) {
    asm volatile("cp.async.cg.shared.global [%0], [%1], 16;\n" :: "r"(dst), "l"(src));
}
#define CP_COMMIT() asm volatile("cp.async.commit_group;\n" ::: "memory")
#define CP_WAIT(n)  asm volatile("cp.async.wait_group %0;\n" :: "n"(n) : "memory")

__device__ __forceinline__ uint32_t smem_u32(const void* p) {
    uint32_t a;
    asm("{ .reg .u64 t; cvta.to.shared.u64 t, %1; cvt.u32.u64 %0, t; }" : "=r"(a) : "l"(p));
    return a;
}

// keep top 10 explicit mantissa bits (exactly fp16-representable in normal range)
__device__ __forceinline__ float hi10(float v) {
    return __uint_as_float(__float_as_uint(v) & 0xFFFFE000u);
}
// pack {low half = eve, high half = odd} as f16x2
__device__ __forceinline__ uint32_t pk(float eve, float odd) {
    uint32_t d;
    asm("cvt.rn.f16x2.f32 %0, %1, %2;" : "=r"(d) : "f"(odd), "f"(eve));
    return d;
}

// mma.sync m16n8k16 fp16 inputs, fp32 accum. Base ISA (sm_80+).
__device__ __forceinline__ void mma_f16(float c[4],
                                        uint32_t a0, uint32_t a1, uint32_t a2, uint32_t a3,
                                        uint32_t b0, uint32_t b1) {
    asm volatile(
        "mma.sync.aligned.m16n8k16.row.col.f32.f16.f16.f32 "
        "{%0,%1,%2,%3}, {%4,%5,%6,%7}, {%8,%9}, {%0,%1,%2,%3};"
        : "+f"(c[0]), "+f"(c[1]), "+f"(c[2]), "+f"(c[3])
        : "r"(a0), "r"(a1), "r"(a2), "r"(a3), "r"(b0), "r"(b1));
}

// ---------------- GEMM1: h = relu(x @ W1 + b1), 3x-fp16 split (round-8 winner) ----------------
#define BM 128
#define BN 128
#define BK 32
#define ASTRIDE 40     // %32==8 -> conflict-free LDS.64 k-pairs
#define BSTRIDE 132    // %32==4 -> conflict-free LDS.32
#define ABYTES (BM * ASTRIDE * 4)     // 20480
#define BBYTES (BK * BSTRIDE * 4)     // 16896
#define STAGEBYTES (ABYTES + BBYTES)  // 37376
#define GSMEM (2 * STAGEBYTES)        // 74752
#define ZPT 96                        // fused zero chunks per CTA

#define SCALE_UP   2048.0f
#define SCALE_DOWN 4.8828125e-4f      // 1/2048

__global__ __launch_bounds__(256) void gemm1_tc(
    const float* __restrict__ A, const float* __restrict__ B,
    const float* __restrict__ bias, float* __restrict__ C,
    float4* __restrict__ zout)
{
    extern __shared__ float smem[];
    const int tid = threadIdx.x;
    const int warp = tid >> 5, lane = tid & 31;
    const int wm = (warp & 1) * 64;       // warp m-offset
    const int wn = (warp >> 1) * 32;      // warp n-offset
    const int row0 = blockIdx.y * BM;
    const int col0 = blockIdx.x * BN;
    const int r = lane >> 2, cq = lane & 3;
    const int ctalin = blockIdx.y * 32 + blockIdx.x;   // 0..1023

    const uint32_t sb = smem_u32(smem);

    if (ctalin == 0 && tid < NEXP) g_counts[tid] = 0;

    float acc_hh[4][4][4];   // [mtile][ntile][frag]
    float acc_cr[4][4][4];   // cross terms, scaled by 2048
    #pragma unroll
    for (int i = 0; i < 4; i++)
        #pragma unroll
        for (int j = 0; j < 4; j++)
            #pragma unroll
            for (int f = 0; f < 4; f++) { acc_hh[i][j][f] = 0.f; acc_cr[i][j][f] = 0.f; }

    auto fill = [&](int buf, int kc) {
        const uint32_t st = sb + buf * STAGEBYTES;
        #pragma unroll
        for (int t = 0; t < 4; t++) {          // A: 1024 x 16B chunks
            int o = tid + t * 256;
            int rr = o >> 3, c16 = o & 7;
            cpasync16(st + (rr * ASTRIDE + c16 * 4) * 4,
                      A + (size_t)(row0 + rr) * HDIM + kc + c16 * 4);
        }
        #pragma unroll
        for (int t = 0; t < 4; t++) {          // B: 1024 x 16B chunks
            int o = tid + t * 256;
            int rr = o >> 5, c16 = o & 31;
            cpasync16(st + ABYTES + (rr * BSTRIDE + c16 * 4) * 4,
                      B + (size_t)(kc + rr) * HDIM + col0 + c16 * 4);
        }
    };

    fill(0, 0);
    CP_COMMIT();

    const float4 z4 = make_float4(0.f, 0.f, 0.f, 0.f);
    const long long zbase = (long long)ctalin * (ZPT * 256) + tid;

    const int NCHUNK = HDIM / BK;   // 128
    for (int c = 0; c < NCHUNK; ++c) {
        if (c < ZPT) zout[zbase + (long long)c * 256] = z4;

        if (c + 1 < NCHUNK) { fill((c + 1) & 1, (c + 1) * BK); CP_COMMIT(); CP_WAIT(1); }
        else                { CP_WAIT(0); }
        __syncthreads();

        const float* As = smem + ((c & 1) * STAGEBYTES) / 4;
        const float* Bs = As + ABYTES / 4;

        #pragma unroll
        for (int kk = 0; kk < 2; kk++) {       // two k16 steps
            const int kof = kk * 16;

            uint32_t ahi[4][4], alo[4][4];
            #pragma unroll
            for (int mt = 0; mt < 4; mt++) {
                const float* pa = As + (size_t)(wm + mt * 16 + r) * ASTRIDE + kof + 2 * cq;
                float2 p0 = *(const float2*)(pa);
                float2 p1 = *(const float2*)(pa + 8 * ASTRIDE);
                float2 p2 = *(const float2*)(pa + 8);
                float2 p3 = *(const float2*)(pa + 8 * ASTRIDE + 8);
                float h;
                h = hi10(p0.x); float l0x = (p0.x - h) * SCALE_UP; float h0x = h;
                h = hi10(p0.y); float l0y = (p0.y - h) * SCALE_UP; float h0y = h;
                h = hi10(p1.x); float l1x = (p1.x - h) * SCALE_UP; float h1x = h;
                h = hi10(p1.y); float l1y = (p1.y - h) * SCALE_UP; float h1y = h;
                h = hi10(p2.x); float l2x = (p2.x - h) * SCALE_UP; float h2x = h;
                h = hi10(p2.y); float l2y = (p2.y - h) * SCALE_UP; float h2y = h;
                h = hi10(p3.x); float l3x = (p3.x - h) * SCALE_UP; float h3x = h;
                h = hi10(p3.y); float l3y = (p3.y - h) * SCALE_UP; float h3y = h;
                ahi[mt][0] = pk(h0x, h0y); alo[mt][0] = pk(l0x, l0y);
                ahi[mt][1] = pk(h1x, h1y); alo[mt][1] = pk(l1x, l1y);
                ahi[mt][2] = pk(h2x, h2y); alo[mt][2] = pk(l2x, l2y);
                ahi[mt][3] = pk(h3x, h3y); alo[mt][3] = pk(l3x, l3y);
            }
            uint32_t bhi[4][2], blo[4][2];
            #pragma unroll
            for (int nt = 0; nt < 4; nt++) {
                const float* pb = Bs + (size_t)(kof + 2 * cq) * BSTRIDE + wn + nt * 8 + r;
                float q0 = pb[0];
                float q1 = pb[BSTRIDE];
                float q2 = pb[8 * BSTRIDE];
                float q3 = pb[9 * BSTRIDE];
                float h;
                h = hi10(q0); float m0 = (q0 - h) * SCALE_UP; float g0 = h;
                h = hi10(q1); float m1 = (q1 - h) * SCALE_UP; float g1 = h;
                h = hi10(q2); float m2 = (q2 - h) * SCALE_UP; float g2 = h;
                h = hi10(q3); float m3 = (q3 - h) * SCALE_UP; float g3 = h;
                bhi[nt][0] = pk(g0, g1); blo[nt][0] = pk(m0, m1);
                bhi[nt][1] = pk(g2, g3); blo[nt][1] = pk(m2, m3);
            }
            #pragma unroll
            for (int mt = 0; mt < 4; mt++)
                #pragma unroll
                for (int nt = 0; nt < 4; nt++)
                    mma_f16(acc_hh[mt][nt], ahi[mt][0], ahi[mt][1], ahi[mt][2], ahi[mt][3],
                            bhi[nt][0], bhi[nt][1]);
            #pragma unroll
            for (int mt = 0; mt < 4; mt++)
                #pragma unroll
                for (int nt = 0; nt < 4; nt++)
                    mma_f16(acc_cr[mt][nt], ahi[mt][0], ahi[mt][1], ahi[mt][2], ahi[mt][3],
                            blo[nt][0], blo[nt][1]);
            #pragma unroll
            for (int mt = 0; mt < 4; mt++)
                #pragma unroll
                for (int nt = 0; nt < 4; nt++)
                    mma_f16(acc_cr[mt][nt], alo[mt][0], alo[mt][1], alo[mt][2], alo[mt][3],
                            bhi[nt][0], bhi[nt][1]);
        }
        __syncthreads();
    }

    // ---- epilogue: relu(hh + cr/2048 + bias) -> C ----
    #pragma unroll
    for (int mt = 0; mt < 4; mt++) {
        #pragma unroll
        for (int nt = 0; nt < 4; nt++) {
            int col = col0 + wn + nt * 8 + 2 * cq;
            float bx = __ldg(bias + col), by = __ldg(bias + col + 1);
            int rowa = row0 + wm + mt * 16 + r;
            float2 v0, v1;
            v0.x = fmaxf(acc_hh[mt][nt][0] + acc_cr[mt][nt][0] * SCALE_DOWN + bx, 0.f);
            v0.y = fmaxf(acc_hh[mt][nt][1] + acc_cr[mt][nt][1] * SCALE_DOWN + by, 0.f);
            v1.x = fmaxf(acc_hh[mt][nt][2] + acc_cr[mt][nt][2] * SCALE_DOWN + bx, 0.f);
            v1.y = fmaxf(acc_hh[mt][nt][3] + acc_cr[mt][nt][3] * SCALE_DOWN + by, 0.f);
            *(float2*)(C + (size_t)rowa * HDIM + col) = v0;
            *(float2*)(C + (size_t)(rowa + 8) * HDIM + col) = v1;
        }
    }
}

// ---------------- GEMM2: logits = h @ W2 + b2, W2 staged transposed in smem ----------------
// Block = 8 warps = 8 tokens. K chunked by 1024; W2 chunk stored as W2T[8][1024+4]
// so per-lane float4 reads are conflict-free (lane stride = 16B).
#define G2_KC 1024
#define G2_PAD 4
__global__ __launch_bounds__(256) void gemm2_kernel(
    const float* __restrict__ h, const float* __restrict__ W2,
    const float* __restrict__ b2, float* __restrict__ logits)
{
    __shared__ float w2t[NEXP][G2_KC + G2_PAD];
    const int tid = threadIdx.x;
    const int wid = tid >> 5, lane = tid & 31;
    const int token = blockIdx.x * 8 + wid;
    const float* hr = h + (size_t)token * HDIM;

    float acc[NEXP];
    #pragma unroll
    for (int e = 0; e < NEXP; e++) acc[e] = 0.f;

    for (int kc0 = 0; kc0 < HDIM; kc0 += G2_KC) {
        // stage W2 chunk transposed: 8192 floats, coalesced reads
        __syncthreads();
        for (int idx = tid; idx < G2_KC * NEXP; idx += 256) {
            int k = idx >> 3, e = idx & 7;
            w2t[e][k] = W2[(size_t)(kc0 + k) * NEXP + e];
        }
        __syncthreads();

        #pragma unroll
        for (int it = 0; it < G2_KC / 128; it++) {
            const int k = it * 128 + lane * 4;
            float4 hv = *(const float4*)(hr + kc0 + k);
            #pragma unroll
            for (int e = 0; e < NEXP; e++) {
                float4 w = *(const float4*)(&w2t[e][k]);
                acc[e] += hv.x * w.x + hv.y * w.y + hv.z * w.z + hv.w * w.w;
            }
        }
    }
    #pragma unroll
    for (int e = 0; e < NEXP; e++) {
        #pragma unroll
        for (int off = 16; off > 0; off >>= 1)
            acc[e] += __shfl_down_sync(0xffffffffu, acc[e], off);
    }
    if (lane == 0) {
        #pragma unroll
        for (int e = 0; e < NEXP; e++)
            logits[token * NEXP + e] = acc[e] + b2[e];
    }
}

// ---------------- softmax + top-2 ----------------
__global__ void topk_kernel(const float* __restrict__ logits, float* __restrict__ probs_out)
{
    int t = blockIdx.x * blockDim.x + threadIdx.x;
    if (t >= NTOK) return;
    float l[NEXP];
    float m = -1e30f;
    #pragma unroll
    for (int e = 0; e < NEXP; e++) { l[e] = logits[t * NEXP + e]; m = fmaxf(m, l[e]); }
    float s = 0.f;
    #pragma unroll
    for (int e = 0; e < NEXP; e++) { l[e] = expf(l[e] - m); s += l[e]; }
    float inv = 1.f / s;
    float p[NEXP];
    #pragma unroll
    for (int e = 0; e < NEXP; e++) { p[e] = l[e] * inv; probs_out[t * NEXP + e] = p[e]; }

    int i1 = 0; float p1 = p[0];
    #pragma unroll
    for (int e = 1; e < NEXP; e++) if (p[e] > p1) { p1 = p[e]; i1 = e; }
    int i2 = -1; float p2 = -1.f;
    #pragma unroll
    for (int e = 0; e < NEXP; e++) if (e != i1 && p[e] > p2) { p2 = p[e]; i2 = e; }

    float norm = 1.f / (p1 + p2 + 1e-8f);
    g_flat_idx[2 * t + 0] = i1;
    g_flat_idx[2 * t + 1] = i2;
    g_flat_prob[2 * t + 0] = p1 * norm;
    g_flat_prob[2 * t + 1] = p2 * norm;
    atomicAdd(&g_counts[i1], 1);
    atomicAdd(&g_counts[i2], 1);
}

// ---------------- exclusive per-expert position scan ----------------
__device__ __forceinline__ uint4 add4(uint4 a, uint4 b) {
    return make_uint4(a.x + b.x, a.y + b.y, a.z + b.z, a.w + b.w);
}
__device__ __forceinline__ uint4 sub4(uint4 a, uint4 b) {
    return make_uint4(a.x - b.x, a.y - b.y, a.z - b.z, a.w - b.w);
}
__global__ __launch_bounds__(1024) void scan_kernel()
{
    const int tid = threadIdx.x;
    const int lane = tid & 31, wid = tid >> 5;

    int e[8];
    uint4 pre[8];
    uint4 run = make_uint4(0, 0, 0, 0);
    #pragma unroll
    for (int i = 0; i < 8; i++) {
        e[i] = g_flat_idx[tid * 8 + i];
        pre[i] = run;
        unsigned word = (unsigned)e[i] >> 1;
        unsigned add = 1u << ((e[i] & 1) * 16);
        if (word == 0) run.x += add;
        else if (word == 1) run.y += add;
        else if (word == 2) run.z += add;
        else run.w += add;
    }
    const uint4 own = run;

    uint4 incl = own;
    #pragma unroll
    for (int off = 1; off < 32; off <<= 1) {
        unsigned vx = __shfl_up_sync(0xffffffffu, incl.x, off);
        unsigned vy = __shfl_up_sync(0xffffffffu, incl.y, off);
        unsigned vz = __shfl_up_sync(0xffffffffu, incl.z, off);
        unsigned vw = __shfl_up_sync(0xffffffffu, incl.w, off);
        if (lane >= off) { incl.x += vx; incl.y += vy; incl.z += vz; incl.w += vw; }
    }

    __shared__ uint4 wtot[32];
    if (lane == 31) wtot[wid] = incl;
    __syncthreads();
    if (wid == 0) {
        uint4 v = wtot[lane];
        uint4 inc2 = v;
        #pragma unroll
        for (int off = 1; off < 32; off <<= 1) {
            unsigned vx = __shfl_up_sync(0xffffffffu, inc2.x, off);
            unsigned vy = __shfl_up_sync(0xffffffffu, inc2.y, off);
            unsigned vz = __shfl_up_sync(0xffffffffu, inc2.z, off);
            unsigned vw = __shfl_up_sync(0xffffffffu, inc2.w, off);
            if (lane >= off) { inc2.x += vx; inc2.y += vy; inc2.z += vz; inc2.w += vw; }
        }
        wtot[lane] = sub4(inc2, v);
    }
    __syncthreads();

    const uint4 base = add4(wtot[wid], sub4(incl, own));
    #pragma unroll
    for (int i = 0; i < 8; i++) {
        uint4 tot = add4(base, pre[i]);
        unsigned word = (unsigned)e[i] >> 1;
        unsigned w = (word == 0) ? tot.x : (word == 1) ? tot.y : (word == 2) ? tot.z : tot.w;
        g_pos[tid * 8 + i] = (int)((w >> ((e[i] & 1) * 16)) & 0xFFFFu);
    }
}

// ---------------- scatter ----------------
__global__ void scatter_kernel(float* __restrict__ dispatch, float* __restrict__ combine)
{
    int n = blockIdx.x * blockDim.x + threadIdx.x;
    if (n >= NSEL) return;
    int p = g_pos[n];
    if (p < CAP) {
        int tok = n >> 1;
        int e = g_flat_idx[n];
        size_t off = ((size_t)tok * NEXP + e) * CAP + p;
        dispatch[off] = 1.0f;
        combine[off] = g_flat_prob[n];
    }
}

// ---------------- aux loss ----------------
__global__ void aux_kernel(const float* __restrict__ probs, float* __restrict__ aux_out)
{
    __shared__ float sh[256];
    const int tid = threadIdx.x;
    float local[NEXP];
    #pragma unroll
    for (int e = 0; e < NEXP; e++) local[e] = 0.f;
    for (int t = tid; t < NTOK; t += 256) {
        #pragma unroll
        for (int e = 0; e < NEXP; e++) local[e] += probs[t * NEXP + e];
    }
    float aux = 0.f;
    for (int e = 0; e < NEXP; e++) {
        sh[tid] = local[e];
        __syncthreads();
        for (int s = 128; s > 0; s >>= 1) {
            if (tid < s) sh[tid] += sh[tid + s];
            __syncthreads();
        }
        if (tid == 0)
            aux += (sh[0] / (float)NTOK) * ((float)g_counts[e] / (float)NSEL) * (float)NEXP;
        __syncthreads();
    }
    if (tid == 0) *aux_out = aux;
}

// ---------------- launch ----------------
extern "C" void kernel_launch(void* const* d_in, const int* in_sizes, int n_in,
                              void* d_out, int out_size)
{
    const float* x  = (const float*)d_in[0];
    const float* W1 = (const float*)d_in[1];
    const float* b1 = (const float*)d_in[2];
    const float* W2 = (const float*)d_in[3];
    const float* b2 = (const float*)d_in[4];

    float* out      = (float*)d_out;
    float* dispatch = out;
    float* combine  = out + DISPATCH_ELEMS;
    float* probs    = out + PROBS_OFF;
    float* aux      = out + AUX_OFF;

    float* d_h;      cudaGetSymbolAddress((void**)&d_h, g_h);
    float* d_logits; cudaGetSymbolAddress((void**)&d_logits, g_logits);

    static bool attr_set = false;
    if (!attr_set) {
        cudaFuncSetAttribute(gemm1_tc, cudaFuncAttributeMaxDynamicSharedMemorySize, GSMEM);
        attr_set = true;
    }

    // 1) GEMM1 (3x-fp16 split mma.sync, round-8) + fused output zeroing
    gemm1_tc<<<dim3(HDIM / BN, NTOK / BM), 256, GSMEM>>>(x, W1, b1, d_h, (float4*)out);

    // 2) GEMM2 with smem-staged transposed W2
    gemm2_kernel<<<NTOK / 8, 256>>>(d_h, W2, b2, d_logits);

    // 3) softmax + top-2
    topk_kernel<<<NTOK / 256, 256>>>(d_logits, probs);

    // 4) capacity position scan
    scan_kernel<<<1, 1024>>>();

    // 5) scatter
    scatter_kernel<<<NSEL / 256, 256>>>(dispatch, combine);

    // 6) aux loss
    aux_kernel<<<1, 256>>>(probs, aux);
}

// round 11
// speedup vs baseline: 1.8695x; 1.2041x over previous
#include <cuda_runtime.h>
#include <cuda.h>
#include <math.h>
#include <cstdint>

// ---------------- problem constants ----------------
#define NTOK   4096          // B*S
#define HDIM   4096
#define NEXP   8
#define TOPK   2
#define CAP    1536
#define NSEL   (NTOK*TOPK)

#define DISPATCH_ELEMS  ((long long)NTOK*NEXP*CAP)
#define PROBS_OFF       (2LL*DISPATCH_ELEMS)
#define AUX_OFF         (PROBS_OFF + (long long)NTOK*NEXP)

// ---------------- device scratch ----------------
__device__ float g_h[(size_t)NTOK * HDIM];
__device__ float g_logits[NTOK * NEXP];
__device__ int   g_flat_idx[NSEL];
__device__ float g_flat_prob[NSEL];
__device__ int   g_pos[NSEL];
__device__ int   g_counts[NEXP];

// ---------------- helpers ----------------
__device__ __forceinline__ void cpasync16(uint32_t dst, const void* src) {
    asm volatile("cp.async.cg.shared.global [%0], [%1], 16;\n" :: "r"(dst), "l"(src));
}
#define CP_COMMIT() asm volatile("cp.async.commit_group;\n" ::: "memory")
#define CP_WAIT(n)  asm volatile("cp.async.wait_group %0;\n" :: "n"(n) : "memory")

__device__ __forceinline__ uint32_t smem_u32(const void* p) {
    uint32_t a;
    asm("{ .reg .u64 t; cvta.to.shared.u64 t, %1; cvt.u32.u64 %0, t; }" : "=r"(a) : "l"(p));
    return a;
}

// keep top 10 explicit mantissa bits (exactly fp16-representable in normal range)
__device__ __forceinline__ float hi10(float v) {
    return __uint_as_float(__float_as_uint(v) & 0xFFFFE000u);
}
// pack {low half = eve, high half = odd} as f16x2 (denormal-correct cvt)
__device__ __forceinline__ uint32_t pk(float eve, float odd) {
    uint32_t d;
    asm("cvt.rn.f16x2.f32 %0, %1, %2;" : "=r"(d) : "f"(odd), "f"(eve));
    return d;
}

// mma.sync m16n8k16 fp16 inputs, fp32 accum. Base ISA (sm_80+).
__device__ __forceinline__ void mma_f16(float c[4],
                                        uint32_t a0, uint32_t a1, uint32_t a2, uint32_t a3,
                                        uint32_t b0, uint32_t b1) {
    asm volatile(
        "mma.sync.aligned.m16n8k16.row.col.f32.f16.f16.f32 "
        "{%0,%1,%2,%3}, {%4,%5,%6,%7}, {%8,%9}, {%0,%1,%2,%3};"
        : "+f"(c[0]), "+f"(c[1]), "+f"(c[2]), "+f"(c[3])
        : "r"(a0), "r"(a1), "r"(a2), "r"(a3), "r"(b0), "r"(b1));
}

// ---------------- GEMM1: h = relu(x @ W1 + b1), 3x-fp16 split, single acc ----------------
// lo terms UNSCALED (fp16 denormals; quantum 2^-24 -> error floor ~4e-6): all three
// products (hh, h*lo, lo*h) accumulate into ONE fp32 acc set -> 64 acc regs ->
// 2 CTAs/SM (4 warps/SMSP) via __launch_bounds__(256, 2).
#define BM 128
#define BN 128
#define BK 32
#define ASTRIDE 40     // %32==8 -> conflict-free LDS.64 k-pairs
#define BSTRIDE 132    // %32==4 -> conflict-free LDS.32
#define ABYTES (BM * ASTRIDE * 4)     // 20480
#define BBYTES (BK * BSTRIDE * 4)     // 16896
#define STAGEBYTES (ABYTES + BBYTES)  // 37376
#define GSMEM (2 * STAGEBYTES)        // 74752
#define ZPT 96                        // fused zero chunks per CTA

__global__ __launch_bounds__(256, 2) void gemm1_tc(
    const float* __restrict__ A, const float* __restrict__ B,
    const float* __restrict__ bias, float* __restrict__ C,
    float4* __restrict__ zout)
{
    extern __shared__ float smem[];
    const int tid = threadIdx.x;
    const int warp = tid >> 5, lane = tid & 31;
    const int wm = (warp & 1) * 64;       // warp m-offset
    const int wn = (warp >> 1) * 32;      // warp n-offset
    const int row0 = blockIdx.y * BM;
    const int col0 = blockIdx.x * BN;
    const int r = lane >> 2, cq = lane & 3;
    const int ctalin = blockIdx.y * 32 + blockIdx.x;   // 0..1023

    const uint32_t sb = smem_u32(smem);

    if (ctalin == 0 && tid < NEXP) g_counts[tid] = 0;

    float acc[4][4][4];   // [mtile][ntile][frag] -- single set
    #pragma unroll
    for (int i = 0; i < 4; i++)
        #pragma unroll
        for (int j = 0; j < 4; j++)
            #pragma unroll
            for (int f = 0; f < 4; f++) acc[i][j][f] = 0.f;

    auto fill = [&](int buf, int kc) {
        const uint32_t st = sb + buf * STAGEBYTES;
        #pragma unroll
        for (int t = 0; t < 4; t++) {          // A: 1024 x 16B chunks
            int o = tid + t * 256;
            int rr = o >> 3, c16 = o & 7;
            cpasync16(st + (rr * ASTRIDE + c16 * 4) * 4,
                      A + (size_t)(row0 + rr) * HDIM + kc + c16 * 4);
        }
        #pragma unroll
        for (int t = 0; t < 4; t++) {          // B: 1024 x 16B chunks
            int o = tid + t * 256;
            int rr = o >> 5, c16 = o & 31;
            cpasync16(st + ABYTES + (rr * BSTRIDE + c16 * 4) * 4,
                      B + (size_t)(kc + rr) * HDIM + col0 + c16 * 4);
        }
    };

    fill(0, 0);
    CP_COMMIT();

    const float4 z4 = make_float4(0.f, 0.f, 0.f, 0.f);
    const long long zbase = (long long)ctalin * (ZPT * 256) + tid;

    const int NCHUNK = HDIM / BK;   // 128
    for (int c = 0; c < NCHUNK; ++c) {
        if (c < ZPT) zout[zbase + (long long)c * 256] = z4;

        if (c + 1 < NCHUNK) { fill((c + 1) & 1, (c + 1) * BK); CP_COMMIT(); CP_WAIT(1); }
        else                { CP_WAIT(0); }
        __syncthreads();

        const float* As = smem + ((c & 1) * STAGEBYTES) / 4;
        const float* Bs = As + ABYTES / 4;

        #pragma unroll
        for (int kk = 0; kk < 2; kk++) {       // two k16 steps
            const int kof = kk * 16;

            // B fragments for all 4 ntiles (live across mt loop): 16 regs
            uint32_t bhi[4][2], blo[4][2];
            #pragma unroll
            for (int nt = 0; nt < 4; nt++) {
                const float* pb = Bs + (size_t)(kof + 2 * cq) * BSTRIDE + wn + nt * 8 + r;
                float q0 = pb[0];
                float q1 = pb[BSTRIDE];
                float q2 = pb[8 * BSTRIDE];
                float q3 = pb[9 * BSTRIDE];
                float h;
                h = hi10(q0); float m0 = q0 - h; float g0 = h;
                h = hi10(q1); float m1 = q1 - h; float g1 = h;
                h = hi10(q2); float m2 = q2 - h; float g2 = h;
                h = hi10(q3); float m3 = q3 - h; float g3 = h;
                bhi[nt][0] = pk(g0, g1); blo[nt][0] = pk(m0, m1);
                bhi[nt][1] = pk(g2, g3); blo[nt][1] = pk(m2, m3);
            }
            // per-mt: split A (8 regs live), then 3 nt-passes into the same acc
            #pragma unroll
            for (int mt = 0; mt < 4; mt++) {
                const float* pa = As + (size_t)(wm + mt * 16 + r) * ASTRIDE + kof + 2 * cq;
                float2 p0 = *(const float2*)(pa);
                float2 p1 = *(const float2*)(pa + 8 * ASTRIDE);
                float2 p2 = *(const float2*)(pa + 8);
                float2 p3 = *(const float2*)(pa + 8 * ASTRIDE + 8);
                float h;
                h = hi10(p0.x); float l0x = p0.x - h; float h0x = h;
                h = hi10(p0.y); float l0y = p0.y - h; float h0y = h;
                h = hi10(p1.x); float l1x = p1.x - h; float h1x = h;
                h = hi10(p1.y); float l1y = p1.y - h; float h1y = h;
                h = hi10(p2.x); float l2x = p2.x - h; float h2x = h;
                h = hi10(p2.y); float l2y = p2.y - h; float h2y = h;
                h = hi10(p3.x); float l3x = p3.x - h; float h3x = h;
                h = hi10(p3.y); float l3y = p3.y - h; float h3y = h;
                uint32_t ah0 = pk(h0x, h0y), al0 = pk(l0x, l0y);
                uint32_t ah1 = pk(h1x, h1y), al1 = pk(l1x, l1y);
                uint32_t ah2 = pk(h2x, h2y), al2 = pk(l2x, l2y);
                uint32_t ah3 = pk(h3x, h3y), al3 = pk(l3x, l3y);

                #pragma unroll
                for (int nt = 0; nt < 4; nt++)
                    mma_f16(acc[mt][nt], ah0, ah1, ah2, ah3, bhi[nt][0], bhi[nt][1]);
                #pragma unroll
                for (int nt = 0; nt < 4; nt++)
                    mma_f16(acc[mt][nt], ah0, ah1, ah2, ah3, blo[nt][0], blo[nt][1]);
                #pragma unroll
                for (int nt = 0; nt < 4; nt++)
                    mma_f16(acc[mt][nt], al0, al1, al2, al3, bhi[nt][0], bhi[nt][1]);
            }
        }
        __syncthreads();
    }

    // ---- epilogue: relu(acc + bias) -> C ----
    #pragma unroll
    for (int mt = 0; mt < 4; mt++) {
        #pragma unroll
        for (int nt = 0; nt < 4; nt++) {
            int col = col0 + wn + nt * 8 + 2 * cq;
            float bx = __ldg(bias + col), by = __ldg(bias + col + 1);
            int rowa = row0 + wm + mt * 16 + r;
            float2 v0, v1;
            v0.x = fmaxf(acc[mt][nt][0] + bx, 0.f);
            v0.y = fmaxf(acc[mt][nt][1] + by, 0.f);
            v1.x = fmaxf(acc[mt][nt][2] + bx, 0.f);
            v1.y = fmaxf(acc[mt][nt][3] + by, 0.f);
            *(float2*)(C + (size_t)rowa * HDIM + col) = v0;
            *(float2*)(C + (size_t)(rowa + 8) * HDIM + col) = v1;
        }
    }
}

// ---------------- GEMM2: logits = h @ W2 + b2, W2 staged transposed in smem ----------------
#define G2_KC 1024
#define G2_PAD 4
__global__ __launch_bounds__(256) void gemm2_kernel(
    const float* __restrict__ h, const float* __restrict__ W2,
    const float* __restrict__ b2, float* __restrict__ logits)
{
    __shared__ float w2t[NEXP][G2_KC + G2_PAD];
    const int tid = threadIdx.x;
    const int wid = tid >> 5, lane = tid & 31;
    const int token = blockIdx.x * 8 + wid;
    const float* hr = h + (size_t)token * HDIM;

    float acc[NEXP];
    #pragma unroll
    for (int e = 0; e < NEXP; e++) acc[e] = 0.f;

    for (int kc0 = 0; kc0 < HDIM; kc0 += G2_KC) {
        __syncthreads();
        for (int idx = tid; idx < G2_KC * NEXP; idx += 256) {
            int k = idx >> 3, e = idx & 7;
            w2t[e][k] = W2[(size_t)(kc0 + k) * NEXP + e];
        }
        __syncthreads();

        #pragma unroll
        for (int it = 0; it < G2_KC / 128; it++) {
            const int k = it * 128 + lane * 4;
            float4 hv = *(const float4*)(hr + kc0 + k);
            #pragma unroll
            for (int e = 0; e < NEXP; e++) {
                float4 w = *(const float4*)(&w2t[e][k]);
                acc[e] += hv.x * w.x + hv.y * w.y + hv.z * w.z + hv.w * w.w;
            }
        }
    }
    #pragma unroll
    for (int e = 0; e < NEXP; e++) {
        #pragma unroll
        for (int off = 16; off > 0; off >>= 1)
            acc[e] += __shfl_down_sync(0xffffffffu, acc[e], off);
    }
    if (lane == 0) {
        #pragma unroll
        for (int e = 0; e < NEXP; e++)
            logits[token * NEXP + e] = acc[e] + b2[e];
    }
}

// ---------------- softmax + top-2 ----------------
__global__ void topk_kernel(const float* __restrict__ logits, float* __restrict__ probs_out)
{
    int t = blockIdx.x * blockDim.x + threadIdx.x;
    if (t >= NTOK) return;
    float l[NEXP];
    float m = -1e30f;
    #pragma unroll
    for (int e = 0; e < NEXP; e++) { l[e] = logits[t * NEXP + e]; m = fmaxf(m, l[e]); }
    float s = 0.f;
    #pragma unroll
    for (int e = 0; e < NEXP; e++) { l[e] = expf(l[e] - m); s += l[e]; }
    float inv = 1.f / s;
    float p[NEXP];
    #pragma unroll
    for (int e = 0; e < NEXP; e++) { p[e] = l[e] * inv; probs_out[t * NEXP + e] = p[e]; }

    int i1 = 0; float p1 = p[0];
    #pragma unroll
    for (int e = 1; e < NEXP; e++) if (p[e] > p1) { p1 = p[e]; i1 = e; }
    int i2 = -1; float p2 = -1.f;
    #pragma unroll
    for (int e = 0; e < NEXP; e++) if (e != i1 && p[e] > p2) { p2 = p[e]; i2 = e; }

    float norm = 1.f / (p1 + p2 + 1e-8f);
    g_flat_idx[2 * t + 0] = i1;
    g_flat_idx[2 * t + 1] = i2;
    g_flat_prob[2 * t + 0] = p1 * norm;
    g_flat_prob[2 * t + 1] = p2 * norm;
    atomicAdd(&g_counts[i1], 1);
    atomicAdd(&g_counts[i2], 1);
}

// ---------------- exclusive per-expert position scan ----------------
__device__ __forceinline__ uint4 add4(uint4 a, uint4 b) {
    return make_uint4(a.x + b.x, a.y + b.y, a.z + b.z, a.w + b.w);
}
__device__ __forceinline__ uint4 sub4(uint4 a, uint4 b) {
    return make_uint4(a.x - b.x, a.y - b.y, a.z - b.z, a.w - b.w);
}
__global__ __launch_bounds__(1024) void scan_kernel()
{
    const int tid = threadIdx.x;
    const int lane = tid & 31, wid = tid >> 5;

    int e[8];
    uint4 pre[8];
    uint4 run = make_uint4(0, 0, 0, 0);
    #pragma unroll
    for (int i = 0; i < 8; i++) {
        e[i] = g_flat_idx[tid * 8 + i];
        pre[i] = run;
        unsigned word = (unsigned)e[i] >> 1;
        unsigned add = 1u << ((e[i] & 1) * 16);
        if (word == 0) run.x += add;
        else if (word == 1) run.y += add;
        else if (word == 2) run.z += add;
        else run.w += add;
    }
    const uint4 own = run;

    uint4 incl = own;
    #pragma unroll
    for (int off = 1; off < 32; off <<= 1) {
        unsigned vx = __shfl_up_sync(0xffffffffu, incl.x, off);
        unsigned vy = __shfl_up_sync(0xffffffffu, incl.y, off);
        unsigned vz = __shfl_up_sync(0xffffffffu, incl.z, off);
        unsigned vw = __shfl_up_sync(0xffffffffu, incl.w, off);
        if (lane >= off) { incl.x += vx; incl.y += vy; incl.z += vz; incl.w += vw; }
    }

    __shared__ uint4 wtot[32];
    if (lane == 31) wtot[wid] = incl;
    __syncthreads();
    if (wid == 0) {
        uint4 v = wtot[lane];
        uint4 inc2 = v;
        #pragma unroll
        for (int off = 1; off < 32; off <<= 1) {
            unsigned vx = __shfl_up_sync(0xffffffffu, inc2.x, off);
            unsigned vy = __shfl_up_sync(0xffffffffu, inc2.y, off);
            unsigned vz = __shfl_up_sync(0xffffffffu, inc2.z, off);
            unsigned vw = __shfl_up_sync(0xffffffffu, inc2.w, off);
            if (lane >= off) { inc2.x += vx; inc2.y += vy; inc2.z += vz; inc2.w += vw; }
        }
        wtot[lane] = sub4(inc2, v);
    }
    __syncthreads();

    const uint4 base = add4(wtot[wid], sub4(incl, own));
    #pragma unroll
    for (int i = 0; i < 8; i++) {
        uint4 tot = add4(base, pre[i]);
        unsigned word = (unsigned)e[i] >> 1;
        unsigned w = (word == 0) ? tot.x : (word == 1) ? tot.y : (word == 2) ? tot.z : tot.w;
        g_pos[tid * 8 + i] = (int)((w >> ((e[i] & 1) * 16)) & 0xFFFFu);
    }
}

// ---------------- scatter ----------------
__global__ void scatter_kernel(float* __restrict__ dispatch, float* __restrict__ combine)
{
    int n = blockIdx.x * blockDim.x + threadIdx.x;
    if (n >= NSEL) return;
    int p = g_pos[n];
    if (p < CAP) {
        int tok = n >> 1;
        int e = g_flat_idx[n];
        size_t off = ((size_t)tok * NEXP + e) * CAP + p;
        dispatch[off] = 1.0f;
        combine[off] = g_flat_prob[n];
    }
}

// ---------------- aux loss ----------------
__global__ void aux_kernel(const float* __restrict__ probs, float* __restrict__ aux_out)
{
    __shared__ float sh[256];
    const int tid = threadIdx.x;
    float local[NEXP];
    #pragma unroll
    for (int e = 0; e < NEXP; e++) local[e] = 0.f;
    for (int t = tid; t < NTOK; t += 256) {
        #pragma unroll
        for (int e = 0; e < NEXP; e++) local[e] += probs[t * NEXP + e];
    }
    float aux = 0.f;
    for (int e = 0; e < NEXP; e++) {
        sh[tid] = local[e];
        __syncthreads();
        for (int s = 128; s > 0; s >>= 1) {
            if (tid < s) sh[tid] += sh[tid + s];
            __syncthreads();
        }
        if (tid == 0)
            aux += (sh[0] / (float)NTOK) * ((float)g_counts[e] / (float)NSEL) * (float)NEXP;
        __syncthreads();
    }
    if (tid == 0) *aux_out = aux;
}

// ---------------- launch ----------------
extern "C" void kernel_launch(void* const* d_in, const int* in_sizes, int n_in,
                              void* d_out, int out_size)
{
    const float* x  = (const float*)d_in[0];
    const float* W1 = (const float*)d_in[1];
    const float* b1 = (const float*)d_in[2];
    const float* W2 = (const float*)d_in[3];
    const float* b2 = (const float*)d_in[4];

    float* out      = (float*)d_out;
    float* dispatch = out;
    float* combine  = out + DISPATCH_ELEMS;
    float* probs    = out + PROBS_OFF;
    float* aux      = out + AUX_OFF;

    float* d_h;      cudaGetSymbolAddress((void**)&d_h, g_h);
    float* d_logits; cudaGetSymbolAddress((void**)&d_logits, g_logits);

    static bool attr_set = false;
    if (!attr_set) {
        cudaFuncSetAttribute(gemm1_tc, cudaFuncAttributeMaxDynamicSharedMemorySize, GSMEM);
        attr_set = true;
    }

    // 1) GEMM1 (3x-fp16 split, single-acc, 2 CTAs/SM) + fused output zeroing
    gemm1_tc<<<dim3(HDIM / BN, NTOK / BM), 256, GSMEM>>>(x, W1, b1, d_h, (float4*)out);

    // 2) GEMM2 with smem-staged transposed W2
    gemm2_kernel<<<NTOK / 8, 256>>>(d_h, W2, b2, d_logits);

    // 3) softmax + top-2
    topk_kernel<<<NTOK / 256, 256>>>(d_logits, probs);

    // 4) capacity position scan
    scan_kernel<<<1, 1024>>>();

    // 5) scatter
    scatter_kernel<<<NSEL / 256, 256>>>(dispatch, combine);

    // 6) aux loss
    aux_kernel<<<1, 256>>>(probs, aux);
}